// round 14
// baseline (speedup 1.0000x reference)
#include <cuda_runtime.h>
#include <cuda_bf16.h>
#include <cuda_fp16.h>
#include <math.h>
#include <stdint.h>

// ---------------- problem constants ----------------
#define TOK   8192
#define DIMD  1024
#define HID   2752
#define NE    8
#define CAP   8192
#define SEG_SH (NE*CAP)
#define ROWS  ((NE+1)*CAP)

#define KT1T  32      // 1024/32 k-tiles (GEMM1)
#define KT2T  86      // 2752/32 k-tiles (GEMM2)
#define NT1   43      // 2752/64  (GEMM1 N-tile 64)
#define NT2   8       // 1024/128 (GEMM2 N-tile 128)
#define MTILES 64     // 8192/128

// ---------------- device scratch ----------------
__device__ int   g_cnt[NE];
__device__ int   g_slot_tok[NE*CAP];
__device__ int   g_tok_slot[TOK*2];
__device__ float g_tok_wt[TOK*2];
__device__ __half g_hhi[(size_t)ROWS*HID];   // hmid fp16 hi
__device__ __half g_hlo[(size_t)ROWS*HID];   // hmid fp16 lo
__device__ float g_y[(size_t)ROWS*DIMD];

// pre-split operands (expert NE slot = shared expert)
__device__ __half s_xh[(size_t)TOK*DIMD];          // x fp16 hi
__device__ __half s_xl[(size_t)TOK*DIMD];          // x fp16 lo
__device__ __half s_w1f[(size_t)(NE+1)*HID*DIMD];  // w1 single fp16
__device__ __half s_w3f[(size_t)(NE+1)*HID*DIMD];  // w3 single fp16
__device__ __half s_w2f[(size_t)(NE+1)*DIMD*HID];  // w2 single fp16

// ---------------- helpers ----------------
__device__ __forceinline__ uint32_t s2u(const void* p){
    uint32_t a;
    asm("{ .reg .u64 t; cvta.to.shared.u64 t, %1; cvt.u32.u64 %0, t; }" : "=r"(a) : "l"(p));
    return a;
}
__device__ __forceinline__ void ldsm_x4(uint32_t r[4], uint32_t addr){
    asm volatile("ldmatrix.sync.aligned.m8n8.x4.shared.b16 {%0,%1,%2,%3}, [%4];"
        : "=r"(r[0]),"=r"(r[1]),"=r"(r[2]),"=r"(r[3]) : "r"(addr));
}
__device__ __forceinline__ void mma_f16(float d[4], const uint32_t a[4], const uint32_t b[2]){
    asm volatile("mma.sync.aligned.m16n8k16.row.col.f32.f16.f16.f32 "
        "{%0,%1,%2,%3}, {%4,%5,%6,%7}, {%8,%9}, {%0,%1,%2,%3};"
        : "+f"(d[0]), "+f"(d[1]), "+f"(d[2]), "+f"(d[3])
        : "r"(a[0]),"r"(a[1]),"r"(a[2]),"r"(a[3]), "r"(b[0]),"r"(b[1]));
}
__device__ __forceinline__ void cpa16(uint32_t dst, const void* src){
    asm volatile("cp.async.cg.shared.global [%0], [%1], 16;" :: "r"(dst), "l"(src));
}
__device__ __forceinline__ void cpa_commit(){ asm volatile("cp.async.commit_group;" ::: "memory"); }
__device__ __forceinline__ void cpa_wait1(){ asm volatile("cp.async.wait_group 1;" ::: "memory"); }
__device__ __forceinline__ uint32_t pack2h(__half a, __half b){
    return (uint32_t)__half_as_ushort(a) | ((uint32_t)__half_as_ushort(b) << 16);
}
__device__ __forceinline__ void splith4(float4 v, uint2& hi, uint2& lo){
    __half h0 = __float2half(v.x), h1 = __float2half(v.y);
    __half h2 = __float2half(v.z), h3 = __float2half(v.w);
    __half l0 = __float2half(v.x - __half2float(h0));
    __half l1 = __float2half(v.y - __half2float(h1));
    __half l2 = __float2half(v.z - __half2float(h2));
    __half l3 = __float2half(v.w - __half2float(h3));
    hi = make_uint2(pack2h(h0,h1), pack2h(h2,h3));
    lo = make_uint2(pack2h(l0,l1), pack2h(l2,l3));
}
__device__ __forceinline__ uint2 cvt4h(float4 v){
    return make_uint2(pack2h(__float2half(v.x), __float2half(v.y)),
                      pack2h(__float2half(v.z), __float2half(v.w)));
}

// ---------------- launch 0: all splits fused (+ cnt zero) ----------------
__global__ void split_all_kernel(const float* __restrict__ w1, const float* __restrict__ sw1,
                                 const float* __restrict__ w3, const float* __restrict__ sw3,
                                 const float* __restrict__ w2, const float* __restrict__ sw2,
                                 const float* __restrict__ x, long wn4, long sn4, long xn4){
    if (blockIdx.x == 0 && threadIdx.x < NE) g_cnt[threadIdx.x] = 0;
    long reg = wn4 + sn4;
    long total = 3*reg + xn4;
    long stride = (long)gridDim.x * blockDim.x;
    for (long i = (long)blockIdx.x*blockDim.x + threadIdx.x; i < total; i += stride){
        if (i < 3*reg){
            int r = (int)(i / reg);
            long k = i - (long)r*reg;
            const float* big   = (r == 0) ? w1  : (r == 1) ? w3  : w2;
            const float* small = (r == 0) ? sw1 : (r == 1) ? sw3 : sw2;
            __half* dst        = (r == 0) ? s_w1f : (r == 1) ? s_w3f : s_w2f;
            float4 v = (k < wn4) ? ((const float4*)big)[k] : ((const float4*)small)[k - wn4];
            ((uint2*)dst)[k] = cvt4h(v);
        } else {
            long di = i - 3*reg;
            float4 v = ((const float4*)x)[di];
            uint2 h, l; splith4(v, h, l);
            ((uint2*)s_xh)[di] = h;
            ((uint2*)s_xl)[di] = l;
        }
    }
}

// ---------------- launch 1: gate ----------------
__global__ void gate_kernel(const float* __restrict__ x, const float* __restrict__ gw){
    int wid = threadIdx.x >> 5, lane = threadIdx.x & 31;
    int t = blockIdx.x * 8 + wid;
    if (t >= TOK) return;
    const float* xr = x + (size_t)t * DIMD;
    float xv[32];
    #pragma unroll
    for (int j = 0; j < 32; j++) xv[j] = xr[j*32 + lane];
    float lg[NE];
    #pragma unroll
    for (int e = 0; e < NE; e++){
        const float* g = gw + e*DIMD;
        float s = 0.f;
        #pragma unroll
        for (int j = 0; j < 32; j++) s += xv[j] * g[j*32 + lane];
        #pragma unroll
        for (int o = 16; o > 0; o >>= 1) s += __shfl_xor_sync(0xffffffffu, s, o);
        lg[e] = s;
    }
    if (lane == 0){
        float m = lg[0];
        #pragma unroll
        for (int e = 1; e < NE; e++) m = fmaxf(m, lg[e]);
        float p[NE], sum = 0.f;
        #pragma unroll
        for (int e = 0; e < NE; e++){ p[e] = expf(lg[e] - m); sum += p[e]; }
        int i0 = 0;
        #pragma unroll
        for (int e = 1; e < NE; e++) if (lg[e] > lg[i0]) i0 = e;
        int i1 = (i0 == 0) ? 1 : 0;
        #pragma unroll
        for (int e = 0; e < NE; e++) if (e != i0 && lg[e] > lg[i1]) i1 = e;
        float w0 = p[i0]/sum, w1 = p[i1]/sum;
        float inv = 1.f / (w0 + w1 + 1e-20f);
        w0 *= inv; w1 *= inv;
        int p0 = atomicAdd(&g_cnt[i0], 1); int s0 = i0*CAP + p0;
        g_slot_tok[s0] = t; g_tok_slot[2*t]   = s0; g_tok_wt[2*t]   = w0;
        int p1 = atomicAdd(&g_cnt[i1], 1); int s1 = i1*CAP + p1;
        g_slot_tok[s1] = t; g_tok_slot[2*t+1] = s1; g_tok_wt[2*t+1] = w1;
    }
}

// ---------------- GEMM1: 2-term fp16, CTA 128x64(x2 mats), warp 64x16, 2 CTAs/SM ----------------
#define G1_AH  0
#define G1_AL  10240
#define G1_B1  20480
#define G1_B3  25600
#define G1_STG 30720
#define G1_SMEM (3*G1_STG)

__global__ void __launch_bounds__(256, 2)
gemm1_kernel(){
    int e = blockIdx.z, mt = blockIdx.y, nt = blockIdx.x;
    bool esh = (e == NE);
    int cnt = esh ? TOK : g_cnt[e];
    int row0 = mt * 128;
    if (row0 >= cnt) return;
    int seg = esh ? SEG_SH : e*CAP;

    extern __shared__ __align__(16) char smem[];
    uint32_t sbase = s2u(smem);

    int tid = threadIdx.x, lane = tid & 31, wid = tid >> 5;
    int wm = wid & 1, wn = wid >> 1;   // wm 0..1 (M 64), wn 0..3 (N 16 per matrix)

    // A loader: 128 rows x 64B (hi,lo)
    int lr = tid >> 1;
    int q  = (tid & 1) * 2;
    int agr = row0 + lr;
    int tA = (agr < cnt) ? (esh ? agr : g_slot_tok[e*CAP + agr]) : 0;
    const __half* pAh = s_xh + (size_t)tA*DIMD + q*8;
    const __half* pAl = s_xl + (size_t)tA*DIMD + q*8;
    uint32_t aoff = (uint32_t)lr*80u + (uint32_t)q*16u;
    // B loaders: 64 rows x 64B each
    int br = tid >> 2;
    int bc = tid & 3;
    size_t wb = (size_t)e*HID*DIMD + (size_t)(nt*64 + br)*DIMD + bc*8;
    const __half* pB1 = s_w1f + wb;
    const __half* pB3 = s_w3f + wb;
    uint32_t boffl = (uint32_t)br*80u + (uint32_t)bc*16u;

    auto load_stage = [&](int st, int kt){
        uint32_t sb = sbase + st*G1_STG;
        int ko = kt*32;
        cpa16(sb+G1_AH+aoff, pAh+ko); cpa16(sb+G1_AH+aoff+16, pAh+ko+8);
        cpa16(sb+G1_AL+aoff, pAl+ko); cpa16(sb+G1_AL+aoff+16, pAl+ko+8);
        cpa16(sb+G1_B1+boffl, pB1+ko);
        cpa16(sb+G1_B3+boffl, pB3+ko);
    };

    float acc1[4][2][4], acc3[4][2][4];
    #pragma unroll
    for (int i=0;i<4;i++)
        #pragma unroll
        for (int j=0;j<2;j++)
            #pragma unroll
            for (int k=0;k<4;k++){ acc1[i][j][k]=0.f; acc3[i][j][k]=0.f; }

    load_stage(0, 0); cpa_commit();
    load_stage(1, 1); cpa_commit();

    int st = 0;
    for (int kt = 0; kt < KT1T; kt++){
        cpa_wait1();
        __syncthreads();
        int st2 = st + 2; if (st2 >= 3) st2 -= 3;
        if (kt + 2 < KT1T) load_stage(st2, kt+2);
        cpa_commit();

        uint32_t sb = sbase + st*G1_STG;
        #pragma unroll
        for (int ks = 0; ks < 2; ks++){
            uint32_t ah[4][4], al[4][4];
            uint32_t acoff = (uint32_t)(ks*32 + ((lane>>4)<<4));
            int arl = wm*64 + (lane & 15);
            #pragma unroll
            for (int i = 0; i < 4; i++){
                uint32_t off = (uint32_t)(arl + i*16)*80u + acoff;
                ldsm_x4(ah[i], sb + G1_AH + off);
                ldsm_x4(al[i], sb + G1_AL + off);
            }
            uint32_t boff = (uint32_t)(wn*16 + (lane>>4)*8 + (lane&7))*80u
                          + (uint32_t)(ks*32 + (((lane>>3)&1)<<4));
            uint32_t b1[4], b3[4];
            ldsm_x4(b1, sb + G1_B1 + boff);
            ldsm_x4(b3, sb + G1_B3 + boff);
            // term-major: Ah terms (16 indep), then Al terms (16 indep)
            #pragma unroll
            for (int j = 0; j < 2; j++){
                #pragma unroll
                for (int i = 0; i < 4; i++) mma_f16(acc1[i][j], ah[i], &b1[j*2]);
                #pragma unroll
                for (int i = 0; i < 4; i++) mma_f16(acc3[i][j], ah[i], &b3[j*2]);
            }
            #pragma unroll
            for (int j = 0; j < 2; j++){
                #pragma unroll
                for (int i = 0; i < 4; i++) mma_f16(acc1[i][j], al[i], &b1[j*2]);
                #pragma unroll
                for (int i = 0; i < 4; i++) mma_f16(acc3[i][j], al[i], &b3[j*2]);
            }
        }
        st = st + 1; if (st >= 3) st -= 3;
    }

    int r0 = lane >> 2;
    int c0 = (lane & 3) * 2;
    #pragma unroll
    for (int i = 0; i < 4; i++){
        #pragma unroll
        for (int rr = 0; rr < 2; rr++){
            int gr = row0 + wm*64 + i*16 + rr*8 + r0;
            if (gr < cnt){
                size_t orow = (size_t)(seg + gr) * HID;
                #pragma unroll
                for (int j = 0; j < 2; j++){
                    int col = nt*64 + wn*16 + j*8 + c0;
                    float a0 = acc1[i][j][rr*2+0], a1 = acc1[i][j][rr*2+1];
                    float b0 = acc3[i][j][rr*2+0], b1 = acc3[i][j][rr*2+1];
                    float v0 = a0 / (1.f + __expf(-a0)) * b0;
                    float v1 = a1 / (1.f + __expf(-a1)) * b1;
                    __half h0 = __float2half(v0), h1 = __float2half(v1);
                    __half l0 = __float2half(v0 - __half2float(h0));
                    __half l1 = __float2half(v1 - __half2float(h1));
                    *(uint32_t*)(g_hhi + orow + col) = pack2h(h0, h1);
                    *(uint32_t*)(g_hlo + orow + col) = pack2h(l0, l1);
                }
            }
        }
    }
}

// ---------------- GEMM2: 2-term fp16, CTA 128x128, warp 64x32, 2 CTAs/SM ----------------
#define G2_AH  0
#define G2_AL  10240
#define G2_B   20480
#define G2_STG 30720
#define G2_SMEM (3*G2_STG)

__global__ void __launch_bounds__(256, 2)
gemm2_kernel(){
    int e = blockIdx.z, mt = blockIdx.y, nt = blockIdx.x;
    bool esh = (e == NE);
    int cnt = esh ? TOK : g_cnt[e];
    int row0 = mt * 128;
    if (row0 >= cnt) return;
    int seg = esh ? SEG_SH : e*CAP;

    extern __shared__ __align__(16) char smem[];
    uint32_t sbase = s2u(smem);

    int tid = threadIdx.x, lane = tid & 31, wid = tid >> 5;
    int wm = wid & 1, wn = wid >> 1;   // wm 0..1 (M 64), wn 0..3 (N 32)

    int lr = tid >> 1;
    int q  = (tid & 1) * 2;
    int agr = row0 + lr;
    int arow = seg + ((agr < cnt) ? agr : 0);
    const __half* pAh = g_hhi + (size_t)arow*HID + q*8;
    const __half* pAl = g_hlo + (size_t)arow*HID + q*8;
    uint32_t aoff = (uint32_t)lr*80u + (uint32_t)q*16u;

    size_t w2b = (size_t)e*DIMD*HID + (size_t)(nt*128 + lr)*HID + q*8;
    const __half* pB = s_w2f + w2b;

    auto load_stage = [&](int st, int kt){
        uint32_t sb = sbase + st*G2_STG;
        int ko = kt*32;
        cpa16(sb+G2_AH+aoff, pAh+ko); cpa16(sb+G2_AH+aoff+16, pAh+ko+8);
        cpa16(sb+G2_AL+aoff, pAl+ko); cpa16(sb+G2_AL+aoff+16, pAl+ko+8);
        cpa16(sb+G2_B +aoff, pB +ko); cpa16(sb+G2_B +aoff+16, pB +ko+8);
    };

    float acc[4][4][4];
    #pragma unroll
    for (int i=0;i<4;i++)
        #pragma unroll
        for (int j=0;j<4;j++)
            #pragma unroll
            for (int k=0;k<4;k++) acc[i][j][k] = 0.f;

    load_stage(0, 0); cpa_commit();
    load_stage(1, 1); cpa_commit();

    int st = 0;
    for (int kt = 0; kt < KT2T; kt++){
        cpa_wait1();
        __syncthreads();
        int st2 = st + 2; if (st2 >= 3) st2 -= 3;
        if (kt + 2 < KT2T) load_stage(st2, kt+2);
        cpa_commit();

        uint32_t sb = sbase + st*G2_STG;
        #pragma unroll
        for (int ks = 0; ks < 2; ks++){
            uint32_t ah[4][4], al[4][4];
            uint32_t acoff = (uint32_t)(ks*32 + ((lane>>4)<<4));
            int arl = wm*64 + (lane & 15);
            #pragma unroll
            for (int i = 0; i < 4; i++){
                uint32_t off = (uint32_t)(arl + i*16)*80u + acoff;
                ldsm_x4(ah[i], sb + G2_AH + off);
                ldsm_x4(al[i], sb + G2_AL + off);
            }
            uint32_t b[2][4];
            #pragma unroll
            for (int jp = 0; jp < 2; jp++){
                uint32_t boff = (uint32_t)(wn*32 + (jp*2 + (lane>>4))*8 + (lane&7))*80u
                              + (uint32_t)(ks*32 + (((lane>>3)&1)<<4));
                ldsm_x4(b[jp], sb + G2_B + boff);
            }
            // term-major: Ah terms (16 indep), then Al terms (16 indep)
            #pragma unroll
            for (int jp = 0; jp < 2; jp++)
                #pragma unroll
                for (int jj = 0; jj < 2; jj++){
                    int j = jp*2 + jj;
                    #pragma unroll
                    for (int i = 0; i < 4; i++) mma_f16(acc[i][j], ah[i], &b[jp][jj*2]);
                }
            #pragma unroll
            for (int jp = 0; jp < 2; jp++)
                #pragma unroll
                for (int jj = 0; jj < 2; jj++){
                    int j = jp*2 + jj;
                    #pragma unroll
                    for (int i = 0; i < 4; i++) mma_f16(acc[i][j], al[i], &b[jp][jj*2]);
                }
        }
        st = st + 1; if (st >= 3) st -= 3;
    }

    int r0 = lane >> 2;
    int c0 = (lane & 3) * 2;
    #pragma unroll
    for (int i = 0; i < 4; i++){
        #pragma unroll
        for (int rr = 0; rr < 2; rr++){
            int gr = row0 + wm*64 + i*16 + rr*8 + r0;
            if (gr < cnt){
                size_t orow = (size_t)(seg + gr) * DIMD;
                #pragma unroll
                for (int j = 0; j < 4; j++){
                    int col = nt*128 + wn*32 + j*8 + c0;
                    float2 v = make_float2(acc[i][j][rr*2+0], acc[i][j][rr*2+1]);
                    *(float2*)(g_y + orow + col) = v;
                }
            }
        }
    }
}

// ---------------- combine ----------------
__global__ void combine_kernel(float* __restrict__ out){
    int t = blockIdx.x;
    int c4 = threadIdx.x;
    int s0 = g_tok_slot[2*t],   s1 = g_tok_slot[2*t+1];
    float w0 = g_tok_wt[2*t],   w1 = g_tok_wt[2*t+1];
    const float4* ysh = (const float4*)(g_y + (size_t)(SEG_SH + t) * DIMD);
    const float4* y0  = (const float4*)(g_y + (size_t)s0 * DIMD);
    const float4* y1  = (const float4*)(g_y + (size_t)s1 * DIMD);
    float4 a = ysh[c4], b = y0[c4], c = y1[c4];
    float4 o;
    o.x = a.x + w0*b.x + w1*c.x;
    o.y = a.y + w0*b.y + w1*c.y;
    o.z = a.z + w0*b.z + w1*c.z;
    o.w = a.w + w0*b.w + w1*c.w;
    ((float4*)(out + (size_t)t * DIMD))[c4] = o;
}

// ---------------- launch ----------------
extern "C" void kernel_launch(void* const* d_in, const int* in_sizes, int n_in,
                              void* d_out, int out_size) {
    const float* x    = (const float*)d_in[0];
    const float* gw   = (const float*)d_in[1];
    const float* w1   = (const float*)d_in[2];
    const float* w3   = (const float*)d_in[3];
    const float* w2   = (const float*)d_in[4];
    const float* sw1  = (const float*)d_in[5];
    const float* sw3  = (const float*)d_in[6];
    const float* sw2  = (const float*)d_in[7];
    float* out = (float*)d_out;

    cudaFuncSetAttribute(gemm1_kernel, cudaFuncAttributeMaxDynamicSharedMemorySize, G1_SMEM);
    cudaFuncSetAttribute(gemm2_kernel, cudaFuncAttributeMaxDynamicSharedMemorySize, G2_SMEM);

    const long WN4 = (long)NE*HID*DIMD/4;
    const long SN4 = (long)HID*DIMD/4;
    const long XN4 = (long)TOK*DIMD/4;
    const int SPLIT_GRID = 1184;   // 148 SMs x 8
    // launches: 0 split_all(+zero), 1 gate, 2 gemm1, 3 gemm2 (<- ncu profiles our index 3)
    split_all_kernel<<<SPLIT_GRID, 256>>>(w1, sw1, w3, sw3, w2, sw2, x, WN4, SN4, XN4);
    gate_kernel<<<TOK/8, 256>>>(x, gw);
    gemm1_kernel<<<dim3(NT1, MTILES, NE+1), 256, G1_SMEM>>>();
    gemm2_kernel<<<dim3(NT2, MTILES, NE+1), 256, G2_SMEM>>>();
    combine_kernel<<<TOK, 256>>>(out);
}

// round 15
// speedup vs baseline: 2.0843x; 2.0843x over previous
#include <cuda_runtime.h>
#include <cuda_bf16.h>
#include <cuda_fp16.h>
#include <math.h>
#include <stdint.h>

// ---------------- problem constants ----------------
#define TOK   8192
#define DIMD  1024
#define HID   2752
#define NE    8
#define CAP   8192
#define SEG_SH (NE*CAP)
#define ROWS  ((NE+1)*CAP)

#define KT1T  32      // 1024/32 k-tiles (GEMM1)
#define KT2T  86      // 2752/32 k-tiles (GEMM2)
#define NT1   22      // ceil(2752/128) (GEMM1 N-tile 128)
#define NT2   4       // 1024/256      (GEMM2 N-tile 256)
#define MTILES 64     // 8192/128

// ---------------- device scratch ----------------
__device__ int   g_cnt[NE];
__device__ int   g_slot_tok[NE*CAP];
__device__ int   g_tok_slot[TOK*2];
__device__ float g_tok_wt[TOK*2];
__device__ __half g_hf[(size_t)ROWS*HID];    // hmid single fp16
__device__ float g_y[(size_t)ROWS*DIMD];

// pre-split operands (expert NE slot = shared expert)
__device__ __half s_xf[(size_t)TOK*DIMD];          // x single fp16
__device__ __half s_w1f[(size_t)(NE+1)*HID*DIMD];  // w1 single fp16
__device__ __half s_w3f[(size_t)(NE+1)*HID*DIMD];  // w3 single fp16
__device__ __half s_w2f[(size_t)(NE+1)*DIMD*HID];  // w2 single fp16

// ---------------- helpers ----------------
__device__ __forceinline__ uint32_t s2u(const void* p){
    uint32_t a;
    asm("{ .reg .u64 t; cvta.to.shared.u64 t, %1; cvt.u32.u64 %0, t; }" : "=r"(a) : "l"(p));
    return a;
}
__device__ __forceinline__ void ldsm_x4(uint32_t r[4], uint32_t addr){
    asm volatile("ldmatrix.sync.aligned.m8n8.x4.shared.b16 {%0,%1,%2,%3}, [%4];"
        : "=r"(r[0]),"=r"(r[1]),"=r"(r[2]),"=r"(r[3]) : "r"(addr));
}
__device__ __forceinline__ void mma_f16(float d[4], const uint32_t a[4], const uint32_t b[2]){
    asm volatile("mma.sync.aligned.m16n8k16.row.col.f32.f16.f16.f32 "
        "{%0,%1,%2,%3}, {%4,%5,%6,%7}, {%8,%9}, {%0,%1,%2,%3};"
        : "+f"(d[0]), "+f"(d[1]), "+f"(d[2]), "+f"(d[3])
        : "r"(a[0]),"r"(a[1]),"r"(a[2]),"r"(a[3]), "r"(b[0]),"r"(b[1]));
}
__device__ __forceinline__ void cpa16(uint32_t dst, const void* src){
    asm volatile("cp.async.cg.shared.global [%0], [%1], 16;" :: "r"(dst), "l"(src));
}
__device__ __forceinline__ void cpa_commit(){ asm volatile("cp.async.commit_group;" ::: "memory"); }
__device__ __forceinline__ void cpa_wait1(){ asm volatile("cp.async.wait_group 1;" ::: "memory"); }
__device__ __forceinline__ uint32_t pack2h(__half a, __half b){
    return (uint32_t)__half_as_ushort(a) | ((uint32_t)__half_as_ushort(b) << 16);
}
__device__ __forceinline__ uint2 cvt4h(float4 v){
    return make_uint2(pack2h(__float2half(v.x), __float2half(v.y)),
                      pack2h(__float2half(v.z), __float2half(v.w)));
}

// ---------------- launch 0: all fp32->fp16 conversions fused (+ cnt zero) ----------------
// region 0: w1|sw1 -> s_w1f, region 1: w3|sw3 -> s_w3f, region 2: w2|sw2 -> s_w2f, region 3: x -> s_xf
__global__ void split_all_kernel(const float* __restrict__ w1, const float* __restrict__ sw1,
                                 const float* __restrict__ w3, const float* __restrict__ sw3,
                                 const float* __restrict__ w2, const float* __restrict__ sw2,
                                 const float* __restrict__ x, long wn4, long sn4, long xn4){
    if (blockIdx.x == 0 && threadIdx.x < NE) g_cnt[threadIdx.x] = 0;
    long reg = wn4 + sn4;
    long total = 3*reg + xn4;
    long stride = (long)gridDim.x * blockDim.x;
    for (long i = (long)blockIdx.x*blockDim.x + threadIdx.x; i < total; i += stride){
        if (i < 3*reg){
            int r = (int)(i / reg);
            long k = i - (long)r*reg;
            const float* big   = (r == 0) ? w1  : (r == 1) ? w3  : w2;
            const float* small = (r == 0) ? sw1 : (r == 1) ? sw3 : sw2;
            __half* dst        = (r == 0) ? s_w1f : (r == 1) ? s_w3f : s_w2f;
            float4 v = (k < wn4) ? ((const float4*)big)[k] : ((const float4*)small)[k - wn4];
            ((uint2*)dst)[k] = cvt4h(v);
        } else {
            long di = i - 3*reg;
            float4 v = ((const float4*)x)[di];
            ((uint2*)s_xf)[di] = cvt4h(v);
        }
    }
}

// ---------------- launch 1: gate ----------------
__global__ void gate_kernel(const float* __restrict__ x, const float* __restrict__ gw){
    int wid = threadIdx.x >> 5, lane = threadIdx.x & 31;
    int t = blockIdx.x * 8 + wid;
    if (t >= TOK) return;
    const float* xr = x + (size_t)t * DIMD;
    float xv[32];
    #pragma unroll
    for (int j = 0; j < 32; j++) xv[j] = xr[j*32 + lane];
    float lg[NE];
    #pragma unroll
    for (int e = 0; e < NE; e++){
        const float* g = gw + e*DIMD;
        float s = 0.f;
        #pragma unroll
        for (int j = 0; j < 32; j++) s += xv[j] * g[j*32 + lane];
        #pragma unroll
        for (int o = 16; o > 0; o >>= 1) s += __shfl_xor_sync(0xffffffffu, s, o);
        lg[e] = s;
    }
    if (lane == 0){
        float m = lg[0];
        #pragma unroll
        for (int e = 1; e < NE; e++) m = fmaxf(m, lg[e]);
        float p[NE], sum = 0.f;
        #pragma unroll
        for (int e = 0; e < NE; e++){ p[e] = expf(lg[e] - m); sum += p[e]; }
        int i0 = 0;
        #pragma unroll
        for (int e = 1; e < NE; e++) if (lg[e] > lg[i0]) i0 = e;
        int i1 = (i0 == 0) ? 1 : 0;
        #pragma unroll
        for (int e = 0; e < NE; e++) if (e != i0 && lg[e] > lg[i1]) i1 = e;
        float w0 = p[i0]/sum, w1 = p[i1]/sum;
        float inv = 1.f / (w0 + w1 + 1e-20f);
        w0 *= inv; w1 *= inv;
        int p0 = atomicAdd(&g_cnt[i0], 1); int s0 = i0*CAP + p0;
        g_slot_tok[s0] = t; g_tok_slot[2*t]   = s0; g_tok_wt[2*t]   = w0;
        int p1 = atomicAdd(&g_cnt[i1], 1); int s1 = i1*CAP + p1;
        g_slot_tok[s1] = t; g_tok_slot[2*t+1] = s1; g_tok_wt[2*t+1] = w1;
    }
}

// ---------------- GEMM1: single fp16, CTA 128x128(x2 mats), warp 64x32, 3-stage ----------------
#define G1_A   0
#define G1_B1  10240
#define G1_B3  20480
#define G1_STG 30720
#define G1_SMEM (3*G1_STG)

__global__ void __launch_bounds__(256, 1)
gemm1_kernel(){
    int e = blockIdx.z, mt = blockIdx.y, nt = blockIdx.x;
    bool esh = (e == NE);
    int cnt = esh ? TOK : g_cnt[e];
    int row0 = mt * 128;
    if (row0 >= cnt) return;
    int seg = esh ? SEG_SH : e*CAP;

    extern __shared__ __align__(16) char smem[];
    uint32_t sbase = s2u(smem);

    int tid = threadIdx.x, lane = tid & 31, wid = tid >> 5;
    int wm = wid & 1, wn = wid >> 1;   // wm 0..1 (M 64), wn 0..3 (N 32 per matrix)

    int lr = tid >> 1;
    int q  = (tid & 1) * 2;
    int agr = row0 + lr;
    int tA = (agr < cnt) ? (esh ? agr : g_slot_tok[e*CAP + agr]) : 0;
    const __half* pA = s_xf + (size_t)tA*DIMD + q*8;
    int brow = nt*128 + lr; if (brow >= HID) brow = HID-1;
    size_t wb = (size_t)e*HID*DIMD + (size_t)brow*DIMD + q*8;
    const __half* pB1 = s_w1f + wb;
    const __half* pB3 = s_w3f + wb;
    uint32_t soff = (uint32_t)lr*80u + (uint32_t)q*16u;

    auto load_stage = [&](int st, int kt){
        uint32_t sb = sbase + st*G1_STG;
        int ko = kt*32;
        cpa16(sb+G1_A +soff, pA +ko); cpa16(sb+G1_A +soff+16, pA +ko+8);
        cpa16(sb+G1_B1+soff, pB1+ko); cpa16(sb+G1_B1+soff+16, pB1+ko+8);
        cpa16(sb+G1_B3+soff, pB3+ko); cpa16(sb+G1_B3+soff+16, pB3+ko+8);
    };

    float acc1[4][4][4], acc3[4][4][4];
    #pragma unroll
    for (int i=0;i<4;i++)
        #pragma unroll
        for (int j=0;j<4;j++)
            #pragma unroll
            for (int k=0;k<4;k++){ acc1[i][j][k]=0.f; acc3[i][j][k]=0.f; }

    load_stage(0, 0); cpa_commit();
    load_stage(1, 1); cpa_commit();

    int st = 0;
    for (int kt = 0; kt < KT1T; kt++){
        cpa_wait1();
        __syncthreads();
        int st2 = st + 2; if (st2 >= 3) st2 -= 3;
        if (kt + 2 < KT1T) load_stage(st2, kt+2);
        cpa_commit();

        uint32_t sb = sbase + st*G1_STG;
        #pragma unroll
        for (int ks = 0; ks < 2; ks++){
            uint32_t ah[4][4];
            uint32_t acoff = (uint32_t)(ks*32 + ((lane>>4)<<4));
            int arl = wm*64 + (lane & 15);
            #pragma unroll
            for (int i = 0; i < 4; i++){
                uint32_t off = (uint32_t)(arl + i*16)*80u + acoff;
                ldsm_x4(ah[i], sb + G1_A + off);
            }
            #pragma unroll
            for (int jp = 0; jp < 2; jp++){
                uint32_t boff = (uint32_t)(wn*32 + (jp*2 + (lane>>4))*8 + (lane&7))*80u
                              + (uint32_t)(ks*32 + (((lane>>3)&1)<<4));
                uint32_t b1[4], b3[4];
                ldsm_x4(b1, sb + G1_B1 + boff);
                ldsm_x4(b3, sb + G1_B3 + boff);
                #pragma unroll
                for (int jj = 0; jj < 2; jj++){
                    int j = jp*2 + jj;
                    #pragma unroll
                    for (int i = 0; i < 4; i++) mma_f16(acc1[i][j], ah[i], &b1[jj*2]);
                    #pragma unroll
                    for (int i = 0; i < 4; i++) mma_f16(acc3[i][j], ah[i], &b3[jj*2]);
                }
            }
        }
        st = st + 1; if (st >= 3) st -= 3;
    }

    int r0 = lane >> 2;
    int c0 = (lane & 3) * 2;
    #pragma unroll
    for (int i = 0; i < 4; i++){
        #pragma unroll
        for (int rr = 0; rr < 2; rr++){
            int gr = row0 + wm*64 + i*16 + rr*8 + r0;
            if (gr < cnt){
                size_t orow = (size_t)(seg + gr) * HID;
                #pragma unroll
                for (int j = 0; j < 4; j++){
                    int col = nt*128 + wn*32 + j*8 + c0;
                    if (col < HID){
                        float a0 = acc1[i][j][rr*2+0], a1 = acc1[i][j][rr*2+1];
                        float b0 = acc3[i][j][rr*2+0], b1 = acc3[i][j][rr*2+1];
                        float v0 = a0 / (1.f + __expf(-a0)) * b0;
                        float v1 = a1 / (1.f + __expf(-a1)) * b1;
                        *(uint32_t*)(g_hf + orow + col) = pack2h(__float2half(v0), __float2half(v1));
                    }
                }
            }
        }
    }
}

// ---------------- GEMM2: single fp16, CTA 128x256, warp 64x64, 3-stage ----------------
#define G2_A   0
#define G2_B   10240
#define G2_STG 30720
#define G2_SMEM (3*G2_STG)

__global__ void __launch_bounds__(256, 1)
gemm2_kernel(){
    int e = blockIdx.z, mt = blockIdx.y, nt = blockIdx.x;
    bool esh = (e == NE);
    int cnt = esh ? TOK : g_cnt[e];
    int row0 = mt * 128;
    if (row0 >= cnt) return;
    int seg = esh ? SEG_SH : e*CAP;

    extern __shared__ __align__(16) char smem[];
    uint32_t sbase = s2u(smem);

    int tid = threadIdx.x, lane = tid & 31, wid = tid >> 5;
    int wm = wid & 1, wn = wid >> 1;   // wm 0..1 (M 64), wn 0..3 (N 64)

    int lr = tid >> 1;
    int q  = (tid & 1) * 2;
    int agr = row0 + lr;
    int arow = seg + ((agr < cnt) ? agr : 0);
    const __half* pA = g_hf + (size_t)arow*HID + q*8;
    uint32_t aoff = (uint32_t)lr*80u + (uint32_t)q*16u;

    size_t w2b = (size_t)e*DIMD*HID + (size_t)(nt*256 + tid)*HID;
    const __half* pB = s_w2f + w2b;
    uint32_t boff2 = (uint32_t)tid*80u;

    auto load_stage = [&](int st, int kt){
        uint32_t sb = sbase + st*G2_STG;
        int ko = kt*32;
        cpa16(sb+G2_A+aoff, pA+ko); cpa16(sb+G2_A+aoff+16, pA+ko+8);
        #pragma unroll
        for (int c = 0; c < 4; c++)
            cpa16(sb+G2_B+boff2+c*16, pB+ko+c*8);
    };

    float acc[4][8][4];
    #pragma unroll
    for (int i=0;i<4;i++)
        #pragma unroll
        for (int j=0;j<8;j++)
            #pragma unroll
            for (int k=0;k<4;k++) acc[i][j][k] = 0.f;

    load_stage(0, 0); cpa_commit();
    load_stage(1, 1); cpa_commit();

    int st = 0;
    for (int kt = 0; kt < KT2T; kt++){
        cpa_wait1();
        __syncthreads();
        int st2 = st + 2; if (st2 >= 3) st2 -= 3;
        if (kt + 2 < KT2T) load_stage(st2, kt+2);
        cpa_commit();

        uint32_t sb = sbase + st*G2_STG;
        #pragma unroll
        for (int ks = 0; ks < 2; ks++){
            uint32_t ah[4][4];
            uint32_t acoff = (uint32_t)(ks*32 + ((lane>>4)<<4));
            int arl = wm*64 + (lane & 15);
            #pragma unroll
            for (int i = 0; i < 4; i++){
                uint32_t off = (uint32_t)(arl + i*16)*80u + acoff;
                ldsm_x4(ah[i], sb + G2_A + off);
            }
            #pragma unroll
            for (int jp = 0; jp < 4; jp++){
                uint32_t boff = (uint32_t)(wn*64 + (jp*2 + (lane>>4))*8 + (lane&7))*80u
                              + (uint32_t)(ks*32 + (((lane>>3)&1)<<4));
                uint32_t b[4];
                ldsm_x4(b, sb + G2_B + boff);
                #pragma unroll
                for (int jj = 0; jj < 2; jj++){
                    int j = jp*2 + jj;
                    #pragma unroll
                    for (int i = 0; i < 4; i++) mma_f16(acc[i][j], ah[i], &b[jj*2]);
                }
            }
        }
        st = st + 1; if (st >= 3) st -= 3;
    }

    int r0 = lane >> 2;
    int c0 = (lane & 3) * 2;
    #pragma unroll
    for (int i = 0; i < 4; i++){
        #pragma unroll
        for (int rr = 0; rr < 2; rr++){
            int gr = row0 + wm*64 + i*16 + rr*8 + r0;
            if (gr < cnt){
                size_t orow = (size_t)(seg + gr) * DIMD;
                #pragma unroll
                for (int j = 0; j < 8; j++){
                    int col = nt*256 + wn*64 + j*8 + c0;
                    float2 v = make_float2(acc[i][j][rr*2+0], acc[i][j][rr*2+1]);
                    *(float2*)(g_y + orow + col) = v;
                }
            }
        }
    }
}

// ---------------- combine ----------------
__global__ void combine_kernel(float* __restrict__ out){
    int t = blockIdx.x;
    int c4 = threadIdx.x;
    int s0 = g_tok_slot[2*t],   s1 = g_tok_slot[2*t+1];
    float w0 = g_tok_wt[2*t],   w1 = g_tok_wt[2*t+1];
    const float4* ysh = (const float4*)(g_y + (size_t)(SEG_SH + t) * DIMD);
    const float4* y0  = (const float4*)(g_y + (size_t)s0 * DIMD);
    const float4* y1  = (const float4*)(g_y + (size_t)s1 * DIMD);
    float4 a = ysh[c4], b = y0[c4], c = y1[c4];
    float4 o;
    o.x = a.x + w0*b.x + w1*c.x;
    o.y = a.y + w0*b.y + w1*c.y;
    o.z = a.z + w0*b.z + w1*c.z;
    o.w = a.w + w0*b.w + w1*c.w;
    ((float4*)(out + (size_t)t * DIMD))[c4] = o;
}

// ---------------- launch ----------------
extern "C" void kernel_launch(void* const* d_in, const int* in_sizes, int n_in,
                              void* d_out, int out_size) {
    const float* x    = (const float*)d_in[0];
    const float* gw   = (const float*)d_in[1];
    const float* w1   = (const float*)d_in[2];
    const float* w3   = (const float*)d_in[3];
    const float* w2   = (const float*)d_in[4];
    const float* sw1  = (const float*)d_in[5];
    const float* sw3  = (const float*)d_in[6];
    const float* sw2  = (const float*)d_in[7];
    float* out = (float*)d_out;

    cudaFuncSetAttribute(gemm1_kernel, cudaFuncAttributeMaxDynamicSharedMemorySize, G1_SMEM);
    cudaFuncSetAttribute(gemm2_kernel, cudaFuncAttributeMaxDynamicSharedMemorySize, G2_SMEM);

    const long WN4 = (long)NE*HID*DIMD/4;
    const long SN4 = (long)HID*DIMD/4;
    const long XN4 = (long)TOK*DIMD/4;
    const int SPLIT_GRID = 1184;   // 148 SMs x 8
    // launches: 0 split_all(+zero), 1 gate, 2 gemm1, 3 gemm2 (<- ncu profiles our index 3)
    split_all_kernel<<<SPLIT_GRID, 256>>>(w1, sw1, w3, sw3, w2, sw2, x, WN4, SN4, XN4);
    gate_kernel<<<TOK/8, 256>>>(x, gw);
    gemm1_kernel<<<dim3(NT1, MTILES, NE+1), 256, G1_SMEM>>>();
    gemm2_kernel<<<dim3(NT2, MTILES, NE+1), 256, G2_SMEM>>>();
    combine_kernel<<<TOK, 256>>>(out);
}